// round 8
// baseline (speedup 1.0000x reference)
#include <cuda_runtime.h>
#include <cstdint>

// ---------------------------------------------------------------------------
// Sparse CNN backbone, fp32, SoA [C][n] features.
// Conv: thread = 2 adjacent rows x SLICE out-channels; all-tap weights in
// <=56KB smem (3 CTAs/SM); chunked gather (MLP 16); BN folded into gather.
// ---------------------------------------------------------------------------

#define MAXN2 80000
#define MAXN4 13824

__device__ float g_xc[MAXN2 * 32];
__device__ float g_z1[MAXN2 * 32];
__device__ float g_z2[MAXN2 * 32];
__device__ float g_y[MAXN4 * 64];
__device__ float g_part[1024 * 64 * 2];
__device__ float g_par[128];

typedef unsigned long long ull;

__device__ __forceinline__ ull pack2(float x) {
    ull r;
    asm("mov.b64 %0, {%1, %1};" : "=l"(r) : "f"(x));
    return r;
}
__device__ __forceinline__ void fma2(ull& d, ull a, ull b) {
    asm("fma.rn.f32x2 %0, %1, %2, %0;" : "+l"(d) : "l"(a), "l"(b));
}

// ---------------------------------------------------------------------------
// SoA conv. fT [CIN][n_in] -> oT [COUT][n_out]. Thread = rows (2t,2t+1) x
// SLICE channels; blockIdx.y slices COUT; 512 rows per CTA.
// TIN: gather applies relu(x*sc+sh) (folds previous BN+ReLU).
// STATS: per-block per-channel (sum,sumsq) partials -> part[bx][64][2].
// ---------------------------------------------------------------------------
template <int CIN, int SLICE, bool TIN, bool STATS>
__global__ __launch_bounds__(256, 3) void conv_p(
    const float* __restrict__ fT, const float* __restrict__ W,
    const int* __restrict__ in_map, const float* __restrict__ bnp,
    int n_in, int n_out, int COUT, float* __restrict__ oT,
    float* __restrict__ part) {
    extern __shared__ float sm[];
    float* sW = sm;                       // [27][CIN][SLICE]
    float* sSc = sm + 27 * CIN * SLICE;   // CIN (TIN)
    float* sSh = sSc + CIN;

    const int tid = threadIdx.x;
    const int yoff = blockIdx.y * SLICE;
    constexpr int WV = SLICE / 4;

    for (int i = tid; i < 27 * CIN * WV; i += 256) {
        int r = i / WV, c4 = (i % WV) * 4;
        reinterpret_cast<float4*>(sW)[i] =
            *reinterpret_cast<const float4*>(W + (size_t)r * COUT + yoff + c4);
    }
    if (TIN) {
        if (tid < CIN) sSc[tid] = bnp[tid];
        else if (tid < 2 * CIN) sSh[tid - CIN] = bnp[tid];
    }
    __syncthreads();

    const int r0 = blockIdx.x * 512 + 2 * tid;
    const int r1 = r0 + 1;
    const bool ok0 = r0 < n_out, ok1 = r1 < n_out;

    ull acc0[SLICE / 2], acc1[SLICE / 2];
#pragma unroll
    for (int i = 0; i < SLICE / 2; i++) { acc0[i] = 0ull; acc1[i] = 0ull; }

    int i0n = ok0 ? __ldg(&in_map[r0]) : n_in;
    int i1n = ok1 ? __ldg(&in_map[r1]) : n_in;

    for (int k = 0; k < 27; k++) {
        const int i0 = i0n, i1 = i1n;
        if (k + 1 < 27) {
            const int* mp = in_map + (size_t)(k + 1) * n_out;
            i0n = ok0 ? __ldg(&mp[r0]) : n_in;
            i1n = ok1 ? __ldg(&mp[r1]) : n_in;
        }
        const bool v0 = i0 < n_in, v1 = i1 < n_in;
        if (__ballot_sync(0xffffffffu, v0 | v1) == 0u) continue;

#pragma unroll
        for (int cc = 0; cc < CIN / 8; cc++) {
            float x0[8], x1[8];
#pragma unroll
            for (int j = 0; j < 8; j++) {
                const float* colp = fT + (size_t)(cc * 8 + j) * n_in;
                float a = v0 ? __ldg(colp + i0) : 0.f;
                float b = v1 ? __ldg(colp + i1) : 0.f;
                if (TIN) {
                    const float sc = sSc[cc * 8 + j], sh = sSh[cc * 8 + j];
                    a = fmaxf(a * sc + sh, 0.f);
                    b = fmaxf(b * sc + sh, 0.f);
                    a = v0 ? a : 0.f;   // re-mask: invalid taps contribute 0
                    b = v1 ? b : 0.f;
                }
                x0[j] = a;
                x1[j] = b;
            }
            const float* wk = sW + ((size_t)k * CIN + cc * 8) * SLICE;
#pragma unroll
            for (int j = 0; j < 8; j++) {
                ull a0 = pack2(x0[j]), a1 = pack2(x1[j]);
                const ulonglong2* wr =
                    reinterpret_cast<const ulonglong2*>(wk + j * SLICE);
#pragma unroll
                for (int p = 0; p < SLICE / 4; p++) {
                    ulonglong2 w = wr[p];
                    fma2(acc0[2 * p], a0, w.x);
                    fma2(acc0[2 * p + 1], a0, w.y);
                    fma2(acc1[2 * p], a1, w.x);
                    fma2(acc1[2 * p + 1], a1, w.y);
                }
            }
        }
    }

    float v0s[SLICE], v1s[SLICE];
#pragma unroll
    for (int p = 0; p < SLICE / 2; p++) {
        float2 a = *reinterpret_cast<float2*>(&acc0[p]);
        v0s[2 * p] = a.x; v0s[2 * p + 1] = a.y;
        float2 b = *reinterpret_cast<float2*>(&acc1[p]);
        v1s[2 * p] = b.x; v1s[2 * p + 1] = b.y;
    }
#pragma unroll
    for (int s = 0; s < SLICE; s++) {
        if (ok0) oT[(size_t)(yoff + s) * n_out + r0] = v0s[s];
        if (ok1) oT[(size_t)(yoff + s) * n_out + r1] = v1s[s];
    }

    if (STATS) {
        __syncthreads();  // done with sW
        float* sv = sm;                  // 256*SLICE
        float* sq = sm + 256 * SLICE;    // 256*SLICE
#pragma unroll
        for (int s = 0; s < SLICE; s++) {
            // rows >= n_out have exact-zero accumulators (all taps invalid)
            sv[tid * SLICE + s] = v0s[s] + v1s[s];
            sq[tid * SLICE + s] = v0s[s] * v0s[s] + v1s[s] * v1s[s];
        }
        __syncthreads();
        constexpr int P = 256 / SLICE;
        const int c = tid % SLICE, gsub = tid / SLICE;
        float S = 0.f, Q = 0.f;
        for (int r = gsub; r < 256; r += P) {
            S += sv[r * SLICE + c];
            Q += sq[r * SLICE + c];
        }
        __syncthreads();
        sv[gsub * SLICE + c] = S;
        sq[gsub * SLICE + c] = Q;
        __syncthreads();
        if (tid < SLICE) {
            float S2 = 0.f, Q2 = 0.f;
#pragma unroll
            for (int r = 0; r < P; r++) {
                S2 += sv[r * SLICE + tid];
                Q2 += sq[r * SLICE + tid];
            }
            part[((size_t)blockIdx.x * 64 + yoff + tid) * 2] = S2;
            part[((size_t)blockIdx.x * 64 + yoff + tid) * 2 + 1] = Q2;
        }
    }
}

// ---------------------------------------------------------------------------
// First conv: CIN=4 (geo ++ col), COUT=32, K=125, ReLU, SoA output.
// ---------------------------------------------------------------------------
__global__ __launch_bounds__(256, 3) void conv1_s(
    const float* __restrict__ geo, const float* __restrict__ col,
    const float* __restrict__ W, const int* __restrict__ in_map, int n_in,
    int n_out, float* __restrict__ oT) {
    extern __shared__ float sm[];
    const int tid = threadIdx.x;
    for (int i = tid; i < 125 * 32; i += 256)
        reinterpret_cast<float4*>(sm)[i] = reinterpret_cast<const float4*>(W)[i];
    __syncthreads();

    const int row = blockIdx.x * 256 + tid;
    if (row >= n_out) return;

    ull acc[16];
#pragma unroll
    for (int i = 0; i < 16; i++) acc[i] = 0ull;

    int idxn = __ldg(&in_map[row]);
    for (int k = 0; k < 125; k++) {
        int idx = idxn;
        if (k + 1 < 125) idxn = __ldg(&in_map[(size_t)(k + 1) * n_out + row]);
        if (idx >= n_in) continue;

        float fr[4];
        fr[0] = __ldg(&geo[idx]);
        fr[1] = __ldg(&col[(size_t)idx * 3]);
        fr[2] = __ldg(&col[(size_t)idx * 3 + 1]);
        fr[3] = __ldg(&col[(size_t)idx * 3 + 2]);
        const float* wk = sm + k * 128;
#pragma unroll
        for (int c = 0; c < 4; c++) {
            ull a2 = pack2(fr[c]);
            const ulonglong2* wrow = reinterpret_cast<const ulonglong2*>(wk + c * 32);
#pragma unroll
            for (int p = 0; p < 8; p++) {
                ulonglong2 w = wrow[p];
                fma2(acc[2 * p], a2, w.x);
                fma2(acc[2 * p + 1], a2, w.y);
            }
        }
    }
#pragma unroll
    for (int p = 0; p < 16; p++) {
        float2 v = *reinterpret_cast<float2*>(&acc[p]);
        oT[(size_t)(2 * p) * n_out + row] = fmaxf(v.x, 0.f);
        oT[(size_t)(2 * p + 1) * n_out + row] = fmaxf(v.y, 0.f);
    }
}

// ---------------------------------------------------------------------------
__global__ __launch_bounds__(256) void bn_reduce(
    const float* __restrict__ part, int nblk, int C, int n,
    const float* __restrict__ g, const float* __restrict__ b,
    float* __restrict__ params) {
    __shared__ float ss[256], sq[256];
    const int t = threadIdx.x;
    const int P = 256 / C;
    const int c = t % C, r = t / C;
    float s = 0.f, q = 0.f;
    for (int i = r; i < nblk; i += P) {
        s += part[((size_t)i * 64 + c) * 2];
        q += part[((size_t)i * 64 + c) * 2 + 1];
    }
    ss[t] = s;
    sq[t] = q;
    __syncthreads();
    for (int o = P / 2; o >= 1; o >>= 1) {
        if (r < o) {
            ss[t] += ss[t + o * C];
            sq[t] += sq[t + o * C];
        }
        __syncthreads();
    }
    if (r == 0) {
        float inv_n = 1.f / (float)n;
        float mu = ss[t] * inv_n;
        float var = sq[t] * inv_n - mu * mu;
        float sc = g[c] * rsqrtf(var + 1e-5f);
        params[c] = sc;
        params[C + c] = b[c] - mu * sc;
    }
}

// SoA: out[c][i] = relu(z[c][i]*sc[c]+sh[c] + res[c][i])
__global__ __launch_bounds__(256) void bn_res_relu_s(
    const float* __restrict__ z, const float* __restrict__ par,
    const float* __restrict__ res, float* __restrict__ out, int n, int C) {
    const int c = blockIdx.y;
    const float sc = par[c], sh = par[C + c];
    const float* zp = z + (size_t)c * n;
    const float* rp = res + (size_t)c * n;
    float* op = out + (size_t)c * n;
    for (int i = blockIdx.x * 256 + threadIdx.x; i < n; i += gridDim.x * 256)
        op[i] = fmaxf(zp[i] * sc + sh + rp[i], 0.f);
}

// Final: relu(bn(z)+res) SoA -> AoS d_out, smem-tiled transpose.
__global__ __launch_bounds__(256) void final_k(
    const float* __restrict__ z, const float* __restrict__ par,
    const float* __restrict__ res, float* __restrict__ out, int n) {
    __shared__ float t[64 * 65];
    const int R0 = blockIdx.x * 64;
    const int tid = threadIdx.x;
    for (int i = tid; i < 4096; i += 256) {
        int c = i >> 6, r = i & 63;
        int row = R0 + r;
        float v = 0.f;
        if (row < n) {
            v = z[(size_t)c * n + row] * par[c] + par[64 + c] +
                res[(size_t)c * n + row];
            v = fmaxf(v, 0.f);
        }
        t[c * 65 + r] = v;
    }
    __syncthreads();
    for (int i = tid; i < 4096; i += 256) {
        int r = i >> 6, c = i & 63;
        int row = R0 + r;
        if (row < n) out[(size_t)row * 64 + c] = t[c * 65 + r];
    }
}

// ---------------------------------------------------------------------------
extern "C" void kernel_launch(void* const* d_in, const int* in_sizes, int n_in,
                              void* d_out, int out_size) {
    const float* x_geo = (const float*)d_in[0];
    const float* x_col = (const float*)d_in[1];
    const float* w0 = (const float*)d_in[2];
    const float* w_e1 = (const float*)d_in[3];
    const float* g_e1 = (const float*)d_in[4];
    const float* b_e1 = (const float*)d_in[5];
    const float* w2 = (const float*)d_in[6];
    const float* w_e2 = (const float*)d_in[7];
    const float* g_e2 = (const float*)d_in[8];
    const float* b_e2 = (const float*)d_in[9];
    const int* m1_in = (const int*)d_in[10];
    const int* m2_in = (const int*)d_in[12];
    const int* m3_in = (const int*)d_in[14];
    const int* m4_in = (const int*)d_in[16];

    const int N = in_sizes[0];
    const int n2 = in_sizes[10] / 125;
    const int n4 = in_sizes[14] / 27;

    float *xc, *z1, *z2, *yb, *part, *par;
    cudaGetSymbolAddress((void**)&xc, g_xc);
    cudaGetSymbolAddress((void**)&z1, g_z1);
    cudaGetSymbolAddress((void**)&z2, g_z2);
    cudaGetSymbolAddress((void**)&yb, g_y);
    cudaGetSymbolAddress((void**)&part, g_part);
    cudaGetSymbolAddress((void**)&par, g_par);

    const int SM1 = 125 * 4 * 32 * 4;                 // 64000
    const int SME1 = (27 * 32 * 16 + 64) * 4;         // 55552 (CIN32 SLICE16)
    const int SMC2 = 27 * 32 * 8 * 4;                 // 27648 (CIN32 SLICE8)
    const int SME2 = (27 * 64 * 8 + 128) * 4;         // 55808 (CIN64 SLICE8)
    cudaFuncSetAttribute(conv1_s, cudaFuncAttributeMaxDynamicSharedMemorySize, SM1);
    cudaFuncSetAttribute(conv_p<32, 16, false, true>, cudaFuncAttributeMaxDynamicSharedMemorySize, SME1);
    cudaFuncSetAttribute(conv_p<32, 16, true, true>, cudaFuncAttributeMaxDynamicSharedMemorySize, SME1);
    cudaFuncSetAttribute(conv_p<32, 8, false, false>, cudaFuncAttributeMaxDynamicSharedMemorySize, SMC2);
    cudaFuncSetAttribute(conv_p<64, 8, false, true>, cudaFuncAttributeMaxDynamicSharedMemorySize, SME2);
    cudaFuncSetAttribute(conv_p<64, 8, true, true>, cudaFuncAttributeMaxDynamicSharedMemorySize, SME2);

    const int gx2 = (n2 + 511) / 512;   // 512 rows/CTA (2 per thread)
    const int gx4 = (n4 + 511) / 512;
    const dim3 ge1(gx2, 2);             // COUT 32, SLICE 16
    const dim3 gc2(gx4, 8);             // COUT 64, SLICE 8
    const dim3 ge2(gx4, 8);
    const dim3 ea1((n2 + 2047) / 2048, 32);
    const dim3 ea2((n4 + 2047) / 2048, 64);

    // conv1 (k5 s2, 4->32) + ReLU -> xc (SoA)
    conv1_s<<<(n2 + 255) / 256, 256, SM1>>>(x_geo, x_col, w0, m1_in, N, n2, xc);

    // enc1: 2 BasicBlocks, 32ch
    for (int i = 0; i < 2; i++) {
        const float* wA = w_e1 + (size_t)(i * 2 + 0) * 27 * 32 * 32;
        const float* wB = w_e1 + (size_t)(i * 2 + 1) * 27 * 32 * 32;
        conv_p<32, 16, false, true><<<ge1, 256, SME1>>>(xc, wA, m2_in, nullptr, n2, n2, 32, z1, part);
        bn_reduce<<<1, 256>>>(part, gx2, 32, n2,
                              g_e1 + (size_t)(i * 2) * 32, b_e1 + (size_t)(i * 2) * 32, par);
        conv_p<32, 16, true, true><<<ge1, 256, SME1>>>(z1, wB, m2_in, par, n2, n2, 32, z2, part);
        bn_reduce<<<1, 256>>>(part, gx2, 32, n2,
                              g_e1 + (size_t)(i * 2 + 1) * 32, b_e1 + (size_t)(i * 2 + 1) * 32, par);
        bn_res_relu_s<<<ea1, 256>>>(z2, par, xc, xc, n2, 32);
    }

    // conv2 (32 -> 64, onto stride-4 coords) -> yb (SoA)
    conv_p<32, 8, false, false><<<gc2, 256, SMC2>>>(xc, w2, m3_in, nullptr, n2, n4, 64, yb, nullptr);

    // enc2: 2 BasicBlocks, 64ch
    for (int i = 0; i < 2; i++) {
        const float* wA = w_e2 + (size_t)(i * 2 + 0) * 27 * 64 * 64;
        const float* wB = w_e2 + (size_t)(i * 2 + 1) * 27 * 64 * 64;
        conv_p<64, 8, false, true><<<ge2, 256, SME2>>>(yb, wA, m4_in, nullptr, n4, n4, 64, z1, part);
        bn_reduce<<<1, 256>>>(part, gx4, 64, n4,
                              g_e2 + (size_t)(i * 2) * 64, b_e2 + (size_t)(i * 2) * 64, par);
        conv_p<64, 8, true, true><<<ge2, 256, SME2>>>(z1, wB, m4_in, par, n4, n4, 64, z2, part);
        bn_reduce<<<1, 256>>>(part, gx4, 64, n4,
                              g_e2 + (size_t)(i * 2 + 1) * 64, b_e2 + (size_t)(i * 2 + 1) * 64, par);
        if (i == 1) {
            final_k<<<(n4 + 63) / 64, 256>>>(z2, par, yb, (float*)d_out, n4);
        } else {
            bn_res_relu_s<<<ea2, 256>>>(z2, par, yb, yb, n4, 64);
        }
    }
}

// round 9
// speedup vs baseline: 1.9331x; 1.9331x over previous
#include <cuda_runtime.h>
#include <cstdint>

// ---------------------------------------------------------------------------
// Sparse CNN backbone, fp32, SoA [C][n] features, K-split convs:
// each conv's 27 (or 125) taps are split across 2 CTA sets writing partial
// sums za/zb; downstream elementwise passes consume (za+zb). Doubles CTA
// parallelism (~24 warps/SM) and halves weight smem (3 CTAs/SM).
// ---------------------------------------------------------------------------

#define MAXN2 80000
#define MAXN4 13824
#define NB 64   // stats blocks per channel

__device__ float g_xc[MAXN2 * 32];   // residual / current (SoA)
__device__ float g_za[MAXN2 * 32];   // conv partial A
__device__ float g_zb[MAXN2 * 32];   // conv partial B
__device__ float g_xt[MAXN2 * 32];   // bn-transformed
__device__ float g_y[MAXN4 * 64];    // enc2 residual
__device__ float g_part[64 * NB * 2];
__device__ float g_par[128];

typedef unsigned long long ull;

__device__ __forceinline__ ull pack2(float x) {
    ull r;
    asm("mov.b64 %0, {%1, %1};" : "=l"(r) : "f"(x));
    return r;
}
__device__ __forceinline__ void fma2(ull& d, ull a, ull b) {
    asm("fma.rn.f32x2 %0, %1, %2, %0;" : "+l"(d) : "l"(a), "l"(b));
}

// ---------------------------------------------------------------------------
// K-split SoA conv. fT [CIN][n_in] -> (za|zb) [COUT][n_out] partial sums.
// blockIdx.z selects tap half; blockIdx.y slices COUT by SLICE.
// Thread = 1 row x SLICE channels; 256 rows/CTA.
// ---------------------------------------------------------------------------
template <int CIN, int SLICE>
__global__ __launch_bounds__(256, 3) void conv_k(
    const float* __restrict__ fT, const float* __restrict__ W,
    const int* __restrict__ in_map, int n_in, int n_out, int COUT,
    int K, int KH, float* __restrict__ oTa, float* __restrict__ oTb) {
    extern __shared__ float sW[];  // [taps][CIN][SLICE]
    const int tid = threadIdx.x;
    const int yoff = blockIdx.y * SLICE;
    const int k0 = blockIdx.z ? KH : 0;
    const int k1 = blockIdx.z ? K : KH;
    const int taps = k1 - k0;
    constexpr int WV = SLICE / 4;

    for (int i = tid; i < taps * CIN * WV; i += 256) {
        int r = i / WV, c4 = (i % WV) * 4;
        reinterpret_cast<float4*>(sW)[i] = *reinterpret_cast<const float4*>(
            W + ((size_t)(k0)*CIN + r) * COUT + yoff + c4);
    }
    __syncthreads();

    const int row = blockIdx.x * 256 + tid;
    const bool rowok = row < n_out;
    float* __restrict__ oT = blockIdx.z ? oTb : oTa;

    ull acc[SLICE / 2];
#pragma unroll
    for (int i = 0; i < SLICE / 2; i++) acc[i] = 0ull;

    int idxn = rowok ? __ldg(&in_map[(size_t)k0 * n_out + row]) : n_in;
    for (int k = k0; k < k1; k++) {
        const int idx = idxn;
        if (k + 1 < k1)
            idxn = rowok ? __ldg(&in_map[(size_t)(k + 1) * n_out + row]) : n_in;
        if (idx >= n_in) continue;

        const float* wk = sW + (size_t)(k - k0) * CIN * SLICE;
#pragma unroll
        for (int cc = 0; cc < CIN / 8; cc++) {
            float x[8];
#pragma unroll
            for (int j = 0; j < 8; j++)
                x[j] = __ldg(fT + (size_t)(cc * 8 + j) * n_in + idx);
#pragma unroll
            for (int j = 0; j < 8; j++) {
                ull a2 = pack2(x[j]);
                const ulonglong2* wr = reinterpret_cast<const ulonglong2*>(
                    wk + (cc * 8 + j) * SLICE);
#pragma unroll
                for (int p = 0; p < SLICE / 4; p++) {
                    ulonglong2 w = wr[p];
                    fma2(acc[2 * p], a2, w.x);
                    fma2(acc[2 * p + 1], a2, w.y);
                }
            }
        }
    }

    if (rowok) {
#pragma unroll
        for (int p = 0; p < SLICE / 2; p++) {
            float2 v = *reinterpret_cast<float2*>(&acc[p]);
            oT[(size_t)(yoff + 2 * p) * n_out + row] = v.x;
            oT[(size_t)(yoff + 2 * p + 1) * n_out + row] = v.y;
        }
    }
}

// ---------------------------------------------------------------------------
// First conv, K-split: CIN=4 (geo ++ col), COUT=32, K=125 -> partial sums.
// ---------------------------------------------------------------------------
__global__ __launch_bounds__(256, 3) void conv1_k(
    const float* __restrict__ geo, const float* __restrict__ col,
    const float* __restrict__ W, const int* __restrict__ in_map, int n_in,
    int n_out, int KH, float* __restrict__ oTa, float* __restrict__ oTb) {
    extern __shared__ float sm[];
    const int tid = threadIdx.x;
    const int k0 = blockIdx.z ? KH : 0;
    const int k1 = blockIdx.z ? 125 : KH;
    const int taps = k1 - k0;

    for (int i = tid; i < taps * 32; i += 256)
        reinterpret_cast<float4*>(sm)[i] =
            reinterpret_cast<const float4*>(W + (size_t)k0 * 128)[i];
    __syncthreads();

    const int row = blockIdx.x * 256 + tid;
    if (row >= n_out) return;
    float* __restrict__ oT = blockIdx.z ? oTb : oTa;

    ull acc[16];
#pragma unroll
    for (int i = 0; i < 16; i++) acc[i] = 0ull;

    int idxn = __ldg(&in_map[(size_t)k0 * n_out + row]);
    for (int k = k0; k < k1; k++) {
        int idx = idxn;
        if (k + 1 < k1) idxn = __ldg(&in_map[(size_t)(k + 1) * n_out + row]);
        if (idx >= n_in) continue;

        float fr[4];
        fr[0] = __ldg(&geo[idx]);
        fr[1] = __ldg(&col[(size_t)idx * 3]);
        fr[2] = __ldg(&col[(size_t)idx * 3 + 1]);
        fr[3] = __ldg(&col[(size_t)idx * 3 + 2]);
        const float* wk = sm + (k - k0) * 128;
#pragma unroll
        for (int c = 0; c < 4; c++) {
            ull a2 = pack2(fr[c]);
            const ulonglong2* wrow = reinterpret_cast<const ulonglong2*>(wk + c * 32);
#pragma unroll
            for (int p = 0; p < 8; p++) {
                ulonglong2 w = wrow[p];
                fma2(acc[2 * p], a2, w.x);
                fma2(acc[2 * p + 1], a2, w.y);
            }
        }
    }
#pragma unroll
    for (int p = 0; p < 16; p++) {
        float2 v = *reinterpret_cast<float2*>(&acc[p]);
        oT[(size_t)(2 * p) * n_out + row] = v.x;
        oT[(size_t)(2 * p + 1) * n_out + row] = v.y;
    }
}

// ---------------------------------------------------------------------------
// Per-(channel, block) stats of (a+b): part[(c*NB + bx)*2 +{0,1}].
// ---------------------------------------------------------------------------
__global__ __launch_bounds__(256) void stats2(
    const float* __restrict__ a, const float* __restrict__ b, int n,
    float* __restrict__ part) {
    __shared__ float sv[256], sq[256];
    const int c = blockIdx.y, tid = threadIdx.x;
    const float* ap = a + (size_t)c * n;
    const float* bp = b + (size_t)c * n;
    float s = 0.f, q = 0.f;
    for (int i = blockIdx.x * 256 + tid; i < n; i += NB * 256) {
        float v = ap[i] + bp[i];
        s += v;
        q += v * v;
    }
    sv[tid] = s;
    sq[tid] = q;
    __syncthreads();
    for (int o = 128; o >= 1; o >>= 1) {
        if (tid < o) {
            sv[tid] += sv[tid + o];
            sq[tid] += sq[tid + o];
        }
        __syncthreads();
    }
    if (tid == 0) {
        part[((size_t)c * NB + blockIdx.x) * 2] = sv[0];
        part[((size_t)c * NB + blockIdx.x) * 2 + 1] = sq[0];
    }
}

// Fold partials -> scale/shift.
__global__ __launch_bounds__(256) void bn_reduce(
    const float* __restrict__ part, int C, int n, const float* __restrict__ g,
    const float* __restrict__ b, float* __restrict__ params) {
    __shared__ float ss[256], sq[256];
    const int t = threadIdx.x;
    const int P = 256 / C;
    const int c = t % C, r = t / C;
    float s = 0.f, q = 0.f;
    for (int i = r; i < NB; i += P) {
        s += part[((size_t)c * NB + i) * 2];
        q += part[((size_t)c * NB + i) * 2 + 1];
    }
    ss[t] = s;
    sq[t] = q;
    __syncthreads();
    for (int o = P / 2; o >= 1; o >>= 1) {
        if (r < o) {
            ss[t] += ss[t + o * C];
            sq[t] += sq[t + o * C];
        }
        __syncthreads();
    }
    if (r == 0) {
        float inv_n = 1.f / (float)n;
        float mu = ss[t] * inv_n;
        float var = sq[t] * inv_n - mu * mu;
        float sc = g[c] * rsqrtf(var + 1e-5f);
        params[c] = sc;
        params[C + c] = b[c] - mu * sc;
    }
}

// xt[c][i] = relu((a+b)*sc+sh)
__global__ __launch_bounds__(256) void apply2(
    const float* __restrict__ a, const float* __restrict__ b,
    const float* __restrict__ par, float* __restrict__ out, int n, int C) {
    const int c = blockIdx.y;
    const float sc = par[c], sh = par[C + c];
    const float* ap = a + (size_t)c * n;
    const float* bp = b + (size_t)c * n;
    float* op = out + (size_t)c * n;
    for (int i = blockIdx.x * 256 + threadIdx.x; i < n; i += gridDim.x * 256)
        op[i] = fmaxf((ap[i] + bp[i]) * sc + sh, 0.f);
}

// out[c][i] = relu((a+b)*sc+sh + res)
__global__ __launch_bounds__(256) void res2(
    const float* __restrict__ a, const float* __restrict__ b,
    const float* __restrict__ par, const float* __restrict__ res,
    float* __restrict__ out, int n, int C) {
    const int c = blockIdx.y;
    const float sc = par[c], sh = par[C + c];
    const float* ap = a + (size_t)c * n;
    const float* bp = b + (size_t)c * n;
    const float* rp = res + (size_t)c * n;
    float* op = out + (size_t)c * n;
    for (int i = blockIdx.x * 256 + threadIdx.x; i < n; i += gridDim.x * 256)
        op[i] = fmaxf((ap[i] + bp[i]) * sc + sh + rp[i], 0.f);
}

// out = relu(a+b) (flat over C*n)
__global__ __launch_bounds__(256) void comb_relu(
    const float* __restrict__ a, const float* __restrict__ b,
    float* __restrict__ out, int total) {
    for (int i = blockIdx.x * 256 + threadIdx.x; i < total; i += gridDim.x * 256)
        out[i] = fmaxf(a[i] + b[i], 0.f);
}

// out = a+b (flat)
__global__ __launch_bounds__(256) void comb_add(
    const float* __restrict__ a, const float* __restrict__ b,
    float* __restrict__ out, int total) {
    for (int i = blockIdx.x * 256 + threadIdx.x; i < total; i += gridDim.x * 256)
        out[i] = a[i] + b[i];
}

// Final: relu((za+zb)*sc+sh + res) SoA -> AoS d_out (smem transpose).
__global__ __launch_bounds__(256) void final2(
    const float* __restrict__ za, const float* __restrict__ zb,
    const float* __restrict__ par, const float* __restrict__ res,
    float* __restrict__ out, int n) {
    __shared__ float t[64 * 65];
    const int R0 = blockIdx.x * 64;
    const int tid = threadIdx.x;
    for (int i = tid; i < 4096; i += 256) {
        int c = i >> 6, r = i & 63;
        int row = R0 + r;
        float v = 0.f;
        if (row < n) {
            size_t o = (size_t)c * n + row;
            v = fmaxf((za[o] + zb[o]) * par[c] + par[64 + c] + res[o], 0.f);
        }
        t[c * 65 + r] = v;
    }
    __syncthreads();
    for (int i = tid; i < 4096; i += 256) {
        int r = i >> 6, c = i & 63;
        int row = R0 + r;
        if (row < n) out[(size_t)row * 64 + c] = t[c * 65 + r];
    }
}

// ---------------------------------------------------------------------------
extern "C" void kernel_launch(void* const* d_in, const int* in_sizes, int n_in,
                              void* d_out, int out_size) {
    const float* x_geo = (const float*)d_in[0];
    const float* x_col = (const float*)d_in[1];
    const float* w0 = (const float*)d_in[2];
    const float* w_e1 = (const float*)d_in[3];
    const float* g_e1 = (const float*)d_in[4];
    const float* b_e1 = (const float*)d_in[5];
    const float* w2 = (const float*)d_in[6];
    const float* w_e2 = (const float*)d_in[7];
    const float* g_e2 = (const float*)d_in[8];
    const float* b_e2 = (const float*)d_in[9];
    const int* m1_in = (const int*)d_in[10];
    const int* m2_in = (const int*)d_in[12];
    const int* m3_in = (const int*)d_in[14];
    const int* m4_in = (const int*)d_in[16];

    const int N = in_sizes[0];
    const int n2 = in_sizes[10] / 125;
    const int n4 = in_sizes[14] / 27;

    float *xc, *za, *zb, *xt, *yb, *part, *par;
    cudaGetSymbolAddress((void**)&xc, g_xc);
    cudaGetSymbolAddress((void**)&za, g_za);
    cudaGetSymbolAddress((void**)&zb, g_zb);
    cudaGetSymbolAddress((void**)&xt, g_xt);
    cudaGetSymbolAddress((void**)&yb, g_y);
    cudaGetSymbolAddress((void**)&part, g_part);
    cudaGetSymbolAddress((void**)&par, g_par);

    const int SM1 = 63 * 4 * 32 * 4;          // 32256
    const int SME1 = 14 * 32 * 32 * 4;        // 57344 (CIN32 SLICE32)
    const int SMC2 = 14 * 32 * 16 * 4;        // 28672 (CIN32 SLICE16)
    const int SME2 = 14 * 64 * 16 * 4;        // 57344 (CIN64 SLICE16)
    cudaFuncSetAttribute(conv1_k, cudaFuncAttributeMaxDynamicSharedMemorySize, SM1);
    cudaFuncSetAttribute(conv_k<32, 32>, cudaFuncAttributeMaxDynamicSharedMemorySize, SME1);
    cudaFuncSetAttribute(conv_k<32, 16>, cudaFuncAttributeMaxDynamicSharedMemorySize, SMC2);
    cudaFuncSetAttribute(conv_k<64, 16>, cudaFuncAttributeMaxDynamicSharedMemorySize, SME2);

    const int gx2 = (n2 + 255) / 256;
    const int gx4 = (n4 + 255) / 256;
    const dim3 gc1(gx2, 1, 2);          // conv1: ksplit 2
    const dim3 ge1(gx2, 1, 2);          // enc1: full COUT32, ksplit 2
    const dim3 gc2(gx4, 4, 2);          // conv2: COUT64/SLICE16, ksplit 2
    const dim3 ge2(gx4, 4, 2);          // enc2
    const dim3 gs1(NB, 32), gs2(NB, 64);
    const dim3 ga1((n2 + 2047) / 2048, 32);
    const dim3 ga2((n4 + 2047) / 2048, 64);
    const int t2 = n2 * 32, t4 = n4 * 64;

    // conv1 (k5 s2, 4->32), ksplit -> relu combine -> xc (SoA)
    conv1_k<<<gc1, 256, SM1>>>(x_geo, x_col, w0, m1_in, N, n2, 63, za, zb);
    comb_relu<<<(t2 + 255) / 256 < 2048 ? (t2 + 255) / 256 : 2048, 256>>>(za, zb, xc, t2);

    // enc1: 2 BasicBlocks, 32ch
    for (int i = 0; i < 2; i++) {
        const float* wA = w_e1 + (size_t)(i * 2 + 0) * 27 * 32 * 32;
        const float* wB = w_e1 + (size_t)(i * 2 + 1) * 27 * 32 * 32;
        conv_k<32, 32><<<ge1, 256, SME1>>>(xc, wA, m2_in, n2, n2, 32, 27, 14, za, zb);
        stats2<<<gs1, 256>>>(za, zb, n2, part);
        bn_reduce<<<1, 256>>>(part, 32, n2,
                              g_e1 + (size_t)(i * 2) * 32, b_e1 + (size_t)(i * 2) * 32, par);
        apply2<<<ga1, 256>>>(za, zb, par, xt, n2, 32);
        conv_k<32, 32><<<ge1, 256, SME1>>>(xt, wB, m2_in, n2, n2, 32, 27, 14, za, zb);
        stats2<<<gs1, 256>>>(za, zb, n2, part);
        bn_reduce<<<1, 256>>>(part, 32, n2,
                              g_e1 + (size_t)(i * 2 + 1) * 32, b_e1 + (size_t)(i * 2 + 1) * 32, par);
        res2<<<ga1, 256>>>(za, zb, par, xc, xc, n2, 32);
    }

    // conv2 (32 -> 64 onto stride-4 coords), ksplit -> add -> yb
    conv_k<32, 16><<<gc2, 256, SMC2>>>(xc, w2, m3_in, n2, n4, 64, 27, 14, za, zb);
    comb_add<<<(t4 + 255) / 256 < 2048 ? (t4 + 255) / 256 : 2048, 256>>>(za, zb, yb, t4);

    // enc2: 2 BasicBlocks, 64ch
    for (int i = 0; i < 2; i++) {
        const float* wA = w_e2 + (size_t)(i * 2 + 0) * 27 * 64 * 64;
        const float* wB = w_e2 + (size_t)(i * 2 + 1) * 27 * 64 * 64;
        conv_k<64, 16><<<ge2, 256, SME2>>>(yb, wA, m4_in, n4, n4, 64, 27, 14, za, zb);
        stats2<<<gs2, 256>>>(za, zb, n4, part);
        bn_reduce<<<1, 256>>>(part, 64, n4,
                              g_e2 + (size_t)(i * 2) * 64, b_e2 + (size_t)(i * 2) * 64, par);
        apply2<<<ga2, 256>>>(za, zb, par, xt, n4, 64);
        conv_k<64, 16><<<ge2, 256, SME2>>>(xt, wB, m4_in, n4, n4, 64, 27, 14, za, zb);
        stats2<<<gs2, 256>>>(za, zb, n4, part);
        bn_reduce<<<1, 256>>>(part, 64, n4,
                              g_e2 + (size_t)(i * 2 + 1) * 64, b_e2 + (size_t)(i * 2 + 1) * 64, par);
        if (i == 1) {
            final2<<<(n4 + 63) / 64, 256>>>(za, zb, par, yb, (float*)d_out, n4);
        } else {
            res2<<<ga2, 256>>>(za, zb, par, yb, yb, n4, 64);
        }
    }
}